// round 7
// baseline (speedup 1.0000x reference)
#include <cuda_runtime.h>
#include <cuda_fp16.h>
#include <cstdint>

// ---------------- problem constants ----------------
#define B_    32
#define CIN   128
#define KNUM  8
#define COUT  128
#define HIDD  512
#define KTOT  1152          // CIN * 9
#define HWTOT 4096          // 64*64
#define NCHUNK 18           // 1152 / 64 (tap-major: 9 taps x 2 channel halves)
#define ROWB  144           // B smem row stride (bytes)
#define BTILE (128 * ROWB)  // 18432 B per B stage
// conv smem layout (dynamic):
#define XSSZ  (6 * 64 * 256)          // 98304 B: 6 image rows x 64 w x 256B (128ch fp16)
#define ZSOFF XSSZ                    // 256 B zero block
#define BSOFF (XSSZ + 256)            // three B stages
#define DYNSM (BSOFF + 3 * BTILE)     // 153856 B

// ---------------- scratch (device globals; no allocs) ----------------
__device__ __align__(16) float  g_pool_part[B_ * 32 * CIN];  // per-tile partial sums
__device__ __align__(16) float  g_alphas[B_ * KNUM];
__device__ __align__(16) float  g_aggb [B_ * COUT];
// agg weights laid out for the conv: [b][chunk(18)][o(128)][cidx(64)] fp16
__device__ __align__(16) __half g_aggw [(size_t)B_ * COUT * KTOT];
// x in NHWC fp16: [b][h][w][c]
__device__ __align__(16) __half g_x16  [(size_t)B_ * HWTOT * CIN];

__device__ __forceinline__ uint32_t smem_u32(const void* p) {
    return (uint32_t)__cvta_generic_to_shared(p);
}
__device__ __forceinline__ float warpsum(float v) {
#pragma unroll
    for (int o = 16; o; o >>= 1) v += __shfl_xor_sync(0xffffffffu, v, o);
    return v;
}

// ================= kernel 1: NCHW fp32 -> NHWC fp16 + per-tile pool partials =========
__global__ void __launch_bounds__(256) convert_kernel(const float* __restrict__ x) {
    __shared__ char sm[128 * 256];
    const int t = threadIdx.x;
    const int tile = blockIdx.x;
    const int pos0 = tile * 128;
    const int b = blockIdx.y;
    const float* xb = x + ((size_t)b * CIN) * HWTOT;

#pragma unroll 4
    for (int i = 0; i < 64; ++i) {
        int e = i * 256 + t;
        int c = e >> 7;
        int p = e & 127;
        float v = xb[(size_t)c * HWTOT + pos0 + p];
        int boff = p * 256 + ((c * 2) ^ ((p & 15) << 4));
        *(__half*)(sm + boff) = __float2half_rn(v);
    }
    __syncthreads();
    if (t < 128) {
        int c = t;
        float s = 0.f;
#pragma unroll 8
        for (int p = 0; p < 128; ++p) {
            int boff = p * 256 + ((c * 2) ^ ((p & 15) << 4));
            s += __half2float(*(const __half*)(sm + boff));
        }
        g_pool_part[(b * 32 + tile) * CIN + c] = s;
    }
    __syncthreads();
    __half* dstb = g_x16 + ((size_t)b * HWTOT + pos0) * CIN;
#pragma unroll
    for (int i = 0; i < 8; ++i) {
        int e = i * 256 + t;
        int p = e >> 4;
        int cc = e & 15;
        int boff = p * 256 + ((cc * 16) ^ ((p & 15) << 4));
        uint4 v = *(const uint4*)(sm + boff);
        ((uint4*)(dstb + (size_t)p * CIN))[cc] = v;
    }
}

// ================= kernel 2: MLP + scores + softmax + bias agg =================
__global__ void mlp_kernel(const float* __restrict__ prompt,
                           const float* __restrict__ w1, const float* __restrict__ b1,
                           const float* __restrict__ w2, const float* __restrict__ b2,
                           const float* __restrict__ kbias) {
    int b = blockIdx.x;
    int tid = threadIdx.x, wid = tid >> 5, lane = tid & 31;
    __shared__ float sp[CIN], sh[HIDD], ss[HIDD], ssc[KNUM], sal[KNUM];
    if (tid < CIN) {
        float s = 0.f;
#pragma unroll 8
        for (int tl = 0; tl < 32; ++tl) s += g_pool_part[(b * 32 + tl) * CIN + tid];
        sp[tid] = s * (1.f / (float)HWTOT);
    }
    __syncthreads();
    for (int j = wid; j < HIDD; j += 16) {
        float p = 0.f;
        for (int c = lane; c < CIN; c += 32) p += sp[c] * w1[j * CIN + c];
        p = warpsum(p);
        if (lane == 0) sh[j] = fmaxf(p + b1[j], 0.f);
    }
    __syncthreads();
    for (int j = wid; j < HIDD; j += 16) {
        float p = 0.f;
        for (int c = lane; c < HIDD; c += 32) p += sh[c] * w2[j * HIDD + c];
        p = warpsum(p);
        if (lane == 0) ss[j] = p + b2[j];
    }
    __syncthreads();
    if (wid < KNUM) {
        float p = 0.f;
        for (int j = lane; j < HIDD; j += 32) p += ss[j] * prompt[wid * HIDD + j];
        p = warpsum(p);
        if (lane == 0) ssc[wid] = p;
    }
    __syncthreads();
    if (tid == 0) {
        float mx = -1e30f;
#pragma unroll
        for (int k = 0; k < KNUM; k++) mx = fmaxf(mx, ssc[k]);
        float den = 0.f, e[KNUM];
#pragma unroll
        for (int k = 0; k < KNUM; k++) { e[k] = expf(ssc[k] - mx); den += e[k]; }
#pragma unroll
        for (int k = 0; k < KNUM; k++) sal[k] = e[k] / den;
    }
    __syncthreads();
    if (tid < KNUM) g_alphas[b * KNUM + tid] = sal[tid];
    if (tid < COUT) {
        float a = 0.f;
#pragma unroll
        for (int k = 0; k < KNUM; k++) a += sal[k] * kbias[k * COUT + tid];
        g_aggb[b * COUT + tid] = a;
    }
}

// ================= kernel 3: weight aggregation v4 (half2, 2 b-groups) =============
__global__ void __launch_bounds__(256) aggw_kernel(const float* __restrict__ kw) {
    __shared__ __align__(4) __half kw_s[KNUM * KTOT];      // 18432 B
    __shared__ float sal[16 * KNUM];
    __shared__ __align__(16) __half out_s[KTOT];
    const int t  = threadIdx.x;
    const int o  = blockIdx.x;
    const int b0 = blockIdx.y * 16;

    // stage kw[k][o][:] fp16, float4-coalesced reads
#pragma unroll
    for (int i = 0; i < 9; ++i) {
        int idx4 = i * 256 + t;            // < 2304 float4
        int k = idx4 / 288;
        int r = idx4 - k * 288;
        float4 v = ((const float4*)kw)[((size_t)k * COUT + o) * 288 + r];
        __half2* d = (__half2*)(kw_s + k * KTOT + r * 4);
        d[0] = __floats2half2_rn(v.x, v.y);
        d[1] = __floats2half2_rn(v.z, v.w);
    }
    if (t < 128) sal[t] = g_alphas[b0 * KNUM + t];
    __syncthreads();

    for (int bb = 0; bb < 16; ++bb) {
#pragma unroll
        for (int i = 0; i < 3; ++i) {
            int jp = i * 256 + t;          // 576 half2 pairs
            if (jp < 576) {
                float a0 = 0.f, a1 = 0.f;
#pragma unroll
                for (int k = 0; k < KNUM; ++k) {
                    float2 wv = __half22float2(*(const __half2*)(kw_s + k * KTOT + jp * 2));
                    float al = sal[bb * KNUM + k];
                    a0 += al * wv.x;
                    a1 += al * wv.y;
                }
                int j0 = jp * 2;
                int ci0 = j0 / 9, tap0 = j0 - ci0 * 9;
                int j1 = j0 + 1;
                int ci1 = j1 / 9, tap1 = j1 - ci1 * 9;
                out_s[(tap0 * 2 + (ci0 >> 6)) * 64 + (ci0 & 63)] = __float2half_rn(a0);
                out_s[(tap1 * 2 + (ci1 >> 6)) * 64 + (ci1 & 63)] = __float2half_rn(a1);
            }
        }
        __syncthreads();
        if (t < 144) {
            int seg = t >> 3, part = t & 7;
            *(uint4*)(g_aggw + (size_t)(b0 + bb) * (COUT * KTOT) + seg * 8192 + o * 64 + part * 8)
                = *(const uint4*)(out_s + seg * 64 + part * 8);
        }
        __syncthreads();
    }
}

// ================= kernel 4: conv — resident-x implicit GEMM (HMMA) =================
__device__ __forceinline__ void ldsm_x4(uint32_t& r0, uint32_t& r1, uint32_t& r2, uint32_t& r3,
                                        uint32_t addr) {
    asm volatile("ldmatrix.sync.aligned.m8n8.x4.shared.b16 {%0,%1,%2,%3}, [%4];"
                 : "=r"(r0), "=r"(r1), "=r"(r2), "=r"(r3) : "r"(addr));
}
__device__ __forceinline__ void mma16816(float* c, uint32_t a0, uint32_t a1, uint32_t a2,
                                         uint32_t a3, uint32_t b0, uint32_t b1) {
    asm volatile(
        "mma.sync.aligned.m16n8k16.row.col.f32.f16.f16.f32 "
        "{%0,%1,%2,%3}, {%4,%5,%6,%7}, {%8,%9}, {%0,%1,%2,%3};"
        : "+f"(c[0]), "+f"(c[1]), "+f"(c[2]), "+f"(c[3])
        : "r"(a0), "r"(a1), "r"(a2), "r"(a3), "r"(b0), "r"(b1));
}
__device__ __forceinline__ void cp16(uint32_t dst, const void* src, uint32_t srcsz) {
    asm volatile("cp.async.cg.shared.global [%0], [%1], 16, %2;"
                 :: "r"(dst), "l"(src), "r"(srcsz) : "memory");
}
__device__ __forceinline__ void cp_commit() {
    asm volatile("cp.async.commit_group;" ::: "memory");
}

extern __shared__ char conv_dyn[];

// CTA = (tile of 256 positions = 4 image rows, sample b). 512 threads, 16 warps.
__global__ void __launch_bounds__(512, 1) conv_kernel(float* __restrict__ out) {
    __shared__ float bias_s[COUT];
    const int t    = threadIdx.x;
    const int wid  = t >> 5;
    const int lane = t & 31;
    const int tile = blockIdx.x;     // 0..15
    const int b    = blockIdx.y;     // 0..31

    if (t < COUT) bias_s[t] = g_aggb[b * COUT + t];

    const uint32_t dynbase = smem_u32(conv_dyn);
    const uint32_t xsb = dynbase;
    const uint32_t zsb = dynbase + ZSOFF;
    const uint32_t bsb = dynbase + BSOFF;

    const __half* xb = g_x16 + (size_t)b * HWTOT * CIN;
    const uint4*  wb = (const uint4*)(g_aggw + (size_t)b * (COUT * KTOT));

    // zero the OOB block
    if (t < 16) *(uint4*)(conv_dyn + ZSOFF + t * 16) = make_uint4(0u, 0u, 0u, 0u);

    // ---- x tile: 6 image rows (tile*4-1 .. tile*4+4), 16B-block XOR swizzle ----
#pragma unroll
    for (int i = 0; i < 12; ++i) {
        int idx = i * 512 + t;               // < 6144 16B-blocks
        int smemrow = idx >> 4;              // 0..383 (lrow*64 + w)
        int blk = idx & 15;
        int lrow = smemrow >> 6;
        int w    = smemrow & 63;
        int srcrow = tile * 4 - 1 + lrow;
        bool v = (unsigned)srcrow < 64u;
        uint32_t dst = xsb + smemrow * 256 + ((blk ^ (smemrow & 15)) << 4);
        const __half* src = v ? (xb + ((size_t)(srcrow * 64 + w) * CIN) + blk * 8) : xb;
        cp16(dst, src, v ? 16u : 0u);
    }

    // ---- B chunk issue (1024 cp16 per chunk, 2 per thread) into 3-stage ring ----
    auto issueB = [&](int kcn) {
        const uint32_t stage = bsb + (uint32_t)(kcn % 3) * BTILE;
        const uint4* wsrc = wb + (size_t)kcn * 1024;
#pragma unroll
        for (int i = 0; i < 2; ++i) {
            int idx = i * 512 + t;
            int g = idx << 4;
            cp16(stage + (g >> 7) * ROWB + (g & 127), (const char*)(wsrc + idx), 16u);
        }
    };

    issueB(0);
    cp_commit();                              // group 0: x tile + B0
    issueB(1);
    cp_commit();                              // group 1: B1

    // warp tiling: 8 (M) x 2 (N); warp tile = M32 x N64
    const int wm = wid >> 1;
    const int wn = wid & 1;
    const int m0 = wm * 32;
    const int n0 = wn * 64;

    float acc[2][8][4];
#pragma unroll
    for (int mt = 0; mt < 2; ++mt)
#pragma unroll
        for (int nt = 0; nt < 8; ++nt)
#pragma unroll
            for (int j = 0; j < 4; ++j) acc[mt][nt][j] = 0.f;

    int mrowhi[2], mpw[2];
#pragma unroll
    for (int mt = 0; mt < 2; ++mt) {
        int m = m0 + mt * 16 + (lane & 15);
        mrowhi[mt] = m >> 6;
        mpw[mt]    = m & 63;
    }
    const int cq = lane >> 4;
    const int g  = lane >> 3;
    const int rs = lane & 7;

    for (int kc = 0; kc < NCHUNK; ++kc) {
        if (kc < NCHUNK - 1) {
            asm volatile("cp.async.wait_group 1;" ::: "memory");
        } else {
            asm volatile("cp.async.wait_group 0;" ::: "memory");
        }
        __syncthreads();                      // stage kc visible to all

        // prefetch stage kc+2 (safe: its buffer was last read at chunk kc-1,
        // and every thread passed the barrier above after finishing kc-1)
        if (kc + 2 < NCHUNK) {
            issueB(kc + 2);
            cp_commit();
        }

        const int tap   = kc >> 1;
        const int chalf = kc & 1;
        const int rtap  = (tap * 11) >> 5;
        const int stap  = tap - rtap * 3;
        const uint32_t smB = bsb + (uint32_t)(kc % 3) * BTILE;

        uint32_t arow[2];
        int akey[2];
#pragma unroll
        for (int mt = 0; mt < 2; ++mt) {
            int lrow = mrowhi[mt] + rtap;
            int iw   = mpw[mt] + stap - 1;
            bool v = (unsigned)iw < 64u;
            int smemrow = lrow * 64 + iw;
            arow[mt] = v ? (xsb + smemrow * 256) : zsb;
            akey[mt] = v ? (smemrow & 15) : 0;
        }

#pragma unroll
        for (int ks = 0; ks < 4; ++ks) {
            const int blk = chalf * 8 + ks * 2 + cq;
            uint32_t A0[4], A1[4];
            ldsm_x4(A0[0], A0[1], A0[2], A0[3], arow[0] + ((blk ^ akey[0]) << 4));
            ldsm_x4(A1[0], A1[1], A1[2], A1[3], arow[1] + ((blk ^ akey[1]) << 4));
#pragma unroll
            for (int bt = 0; bt < 4; ++bt) {
                uint32_t b0e, b1e, b0o, b1o;
                uint32_t baddr = smB + (n0 + bt * 16 + ((g >> 1) << 3) + rs) * ROWB
                               + (ks << 5) + ((g & 1) << 4);
                ldsm_x4(b0e, b1e, b0o, b1o, baddr);
                mma16816(acc[0][2 * bt],     A0[0], A0[1], A0[2], A0[3], b0e, b1e);
                mma16816(acc[0][2 * bt + 1], A0[0], A0[1], A0[2], A0[3], b0o, b1o);
                mma16816(acc[1][2 * bt],     A1[0], A1[1], A1[2], A1[3], b0e, b1e);
                mma16816(acc[1][2 * bt + 1], A1[0], A1[1], A1[2], A1[3], b0o, b1o);
            }
        }
        // no tail barrier: next iteration's issueB targets a stage not in use,
        // and the next visibility barrier orders it for consumers
    }
    __syncthreads();                          // protect x region before F overwrite

    // ---- epilogue: 4 rounds (2 pos-halves x 2 o-halves) via smem transpose ----
    float* F = (float*)conv_dyn;              // 128 x 66 floats (reuses x region)
    float* outb = out + (size_t)b * COUT * HWTOT + tile * 256;
#pragma unroll
    for (int pr = 0; pr < 2; ++pr) {
#pragma unroll
        for (int orr = 0; orr < 2; ++orr) {
            if ((wm >> 2) == pr && wn == orr) {
#pragma unroll
                for (int mt = 0; mt < 2; ++mt)
#pragma unroll
                    for (int nt = 0; nt < 8; ++nt) {
                        int row = m0 - pr * 128 + mt * 16 + (lane >> 2);
                        int col = nt * 8 + 2 * (lane & 3);
                        *(float2*)&F[row * 66 + col]       = make_float2(acc[mt][nt][0], acc[mt][nt][1]);
                        *(float2*)&F[(row + 8) * 66 + col] = make_float2(acc[mt][nt][2], acc[mt][nt][3]);
                    }
            }
            __syncthreads();
#pragma unroll
            for (int i = 0; i < 4; ++i) {
                int e4 = i * 2048 + t * 4;
                int ol = e4 >> 7;
                int pp = e4 & 127;
                int oo = orr * 64 + ol;
                float4 v;
                v.x = F[(pp + 0) * 66 + ol] + bias_s[oo];
                v.y = F[(pp + 1) * 66 + ol] + bias_s[oo];
                v.z = F[(pp + 2) * 66 + ol] + bias_s[oo];
                v.w = F[(pp + 3) * 66 + ol] + bias_s[oo];
                *(float4*)(outb + (size_t)oo * HWTOT + pr * 128 + pp) = v;
            }
            __syncthreads();
        }
    }
}

// ================= launch =================
extern "C" void kernel_launch(void* const* d_in, const int* in_sizes, int n_in,
                              void* d_out, int out_size) {
    (void)out_size;
    const float* x = nullptr; const float* prompt = nullptr;
    const float* w1 = nullptr; const float* b1 = nullptr;
    const float* w2 = nullptr; const float* b2 = nullptr;
    const float* kw = nullptr; const float* kb = nullptr;
    for (int i = 0; i < n_in; ++i) {
        const float* ptr = (const float*)d_in[i];
        switch (in_sizes[i]) {
            case 16777216: x = ptr; break;
            case 4096:     prompt = ptr; break;
            case 65536:    w1 = ptr; break;
            case 262144:   w2 = ptr; break;
            case 1179648:  kw = ptr; break;
            case 1024:     kb = ptr; break;
            case 512:      if (!b1) b1 = ptr; else b2 = ptr; break;
            default: break;
        }
    }
    float* out = (float*)d_out;

    static bool attr_set = false;
    if (!attr_set) {
        cudaFuncSetAttribute(conv_kernel, cudaFuncAttributeMaxDynamicSharedMemorySize, DYNSM);
        attr_set = true;
    }

    convert_kernel<<<dim3(HWTOT / 128, B_), 256>>>(x);
    mlp_kernel<<<B_, 512>>>(prompt, w1, b1, w2, b2, kb);
    aggw_kernel<<<dim3(COUT, 2), 256>>>(kw);
    conv_kernel<<<dim3(HWTOT / 256, B_), 512, DYNSM>>>(out);
}

// round 8
// speedup vs baseline: 1.0892x; 1.0892x over previous
#include <cuda_runtime.h>
#include <cuda_fp16.h>
#include <cstdint>

// ---------------- problem constants ----------------
#define B_    32
#define CIN   128
#define KNUM  8
#define COUT  128
#define HIDD  512
#define KTOT  1152          // CIN * 9
#define HWTOT 4096          // 64*64
#define NCHUNK 18           // 1152 / 64 (tap-major: 9 taps x 2 channel halves)
// conv smem: x tile only (4 image rows x 64 w x 256B) + 256B zero block
#define XSSZ  (4 * 64 * 256)          // 65536
#define ZOFF  XSSZ
#define DYNSM (XSSZ + 256)            // 65792 -> 2 CTAs/SM

// ---------------- scratch (device globals; no allocs) ----------------
__device__ __align__(16) float  g_pool_part[B_ * 32 * CIN];
__device__ __align__(16) float  g_alphas[B_ * KNUM];
__device__ __align__(16) float  g_aggb [B_ * COUT];
// agg weights, conv chunk layout: [b][kc(18)][o(128)][kk(64)] fp16
__device__ __align__(16) __half g_aggw [(size_t)B_ * COUT * KTOT];
// fragment-permuted weights: [b][kc][wn(2)][ks(4)][bt(4)][lane(32)] x uint4
__device__ __align__(16) uint4  g_aggw2[(size_t)B_ * NCHUNK * 1024];
// x in NHWC fp16: [b][h][w][c]
__device__ __align__(16) __half g_x16  [(size_t)B_ * HWTOT * CIN];

__device__ __forceinline__ uint32_t smem_u32(const void* p) {
    return (uint32_t)__cvta_generic_to_shared(p);
}
__device__ __forceinline__ float warpsum(float v) {
#pragma unroll
    for (int o = 16; o; o >>= 1) v += __shfl_xor_sync(0xffffffffu, v, o);
    return v;
}

// ================= kernel 1: NCHW fp32 -> NHWC fp16 + pool partials ==============
// 4B-granularity XOR swizzle: half of channel c, position p lives at byte
//   p*256 + ((2c) ^ ((p&31)<<2))   -> conflict-free stores, pools, and reads.
__global__ void __launch_bounds__(256) convert_kernel(const float* __restrict__ x) {
    __shared__ char sm[128 * 256];
    const int t = threadIdx.x;
    const int tile = blockIdx.x;
    const int pos0 = tile * 128;
    const int b = blockIdx.y;
    const float* xb = x + ((size_t)b * CIN) * HWTOT;

    // read phase: coalesced along positions; conflict-free STS.16
#pragma unroll 4
    for (int i = 0; i < 64; ++i) {
        int e = i * 256 + t;          // 16384 elements
        int c = e >> 7;
        int p = e & 127;
        float v = xb[(size_t)c * HWTOT + pos0 + p];
        int boff = p * 256 + ((c * 2) ^ ((p & 31) << 2));
        *(__half*)(sm + boff) = __float2half_rn(v);
    }
    __syncthreads();

    // pooling: thread t<64 owns channel pair (2t, 2t+1); word loads, conflict-free
    if (t < 64) {
        float s0 = 0.f, s1 = 0.f;
#pragma unroll 8
        for (int p = 0; p < 128; ++p) {
            int boff = p * 256 + ((t * 4) ^ ((p & 31) << 2));
            __half2 h = *(const __half2*)(sm + boff);
            float2 f = __half22float2(h);
            s0 += f.x; s1 += f.y;
        }
        g_pool_part[(b * 32 + tile) * CIN + 2 * t]     = s0;
        g_pool_part[(b * 32 + tile) * CIN + 2 * t + 1] = s1;
    }
    __syncthreads();

    // write phase: word-granular, conflict-free LDS.32, coalesced STG.32
    uint32_t* dstw = (uint32_t*)(g_x16 + ((size_t)b * HWTOT + pos0) * CIN);
#pragma unroll
    for (int i = 0; i < 32; ++i) {
        int e = i * 256 + t;          // 8192 words
        int p = e >> 6;
        int wj = e & 63;
        uint32_t w = *(const uint32_t*)(sm + p * 256 + ((wj * 4) ^ ((p & 31) << 2)));
        dstw[p * 64 + wj] = w;
    }
}

// ================= kernel 2: MLP + scores + softmax + bias agg =================
__global__ void mlp_kernel(const float* __restrict__ prompt,
                           const float* __restrict__ w1, const float* __restrict__ b1,
                           const float* __restrict__ w2, const float* __restrict__ b2,
                           const float* __restrict__ kbias) {
    int b = blockIdx.x;
    int tid = threadIdx.x, wid = tid >> 5, lane = tid & 31;
    __shared__ float sp[CIN], sh[HIDD], ss[HIDD], ssc[KNUM], sal[KNUM];
    if (tid < CIN) {
        float s = 0.f;
#pragma unroll 8
        for (int tl = 0; tl < 32; ++tl) s += g_pool_part[(b * 32 + tl) * CIN + tid];
        sp[tid] = s * (1.f / (float)HWTOT);
    }
    __syncthreads();
    for (int j = wid; j < HIDD; j += 16) {
        float p = 0.f;
        for (int c = lane; c < CIN; c += 32) p += sp[c] * w1[j * CIN + c];
        p = warpsum(p);
        if (lane == 0) sh[j] = fmaxf(p + b1[j], 0.f);
    }
    __syncthreads();
    for (int j = wid; j < HIDD; j += 16) {
        float p = 0.f;
        for (int c = lane; c < HIDD; c += 32) p += sh[c] * w2[j * HIDD + c];
        p = warpsum(p);
        if (lane == 0) ss[j] = p + b2[j];
    }
    __syncthreads();
    if (wid < KNUM) {
        float p = 0.f;
        for (int j = lane; j < HIDD; j += 32) p += ss[j] * prompt[wid * HIDD + j];
        p = warpsum(p);
        if (lane == 0) ssc[wid] = p;
    }
    __syncthreads();
    if (tid == 0) {
        float mx = -1e30f;
#pragma unroll
        for (int k = 0; k < KNUM; k++) mx = fmaxf(mx, ssc[k]);
        float den = 0.f, e[KNUM];
#pragma unroll
        for (int k = 0; k < KNUM; k++) { e[k] = expf(ssc[k] - mx); den += e[k]; }
#pragma unroll
        for (int k = 0; k < KNUM; k++) sal[k] = e[k] / den;
    }
    __syncthreads();
    if (tid < KNUM) g_alphas[b * KNUM + tid] = sal[tid];
    if (tid < COUT) {
        float a = 0.f;
#pragma unroll
        for (int k = 0; k < KNUM; k++) a += sal[k] * kbias[k * COUT + tid];
        g_aggb[b * COUT + tid] = a;
    }
}

// ================= kernel 3: weight aggregation (half2, 2 b-groups) ==============
__global__ void __launch_bounds__(256) aggw_kernel(const float* __restrict__ kw) {
    __shared__ __align__(4) __half kw_s[KNUM * KTOT];
    __shared__ float sal[16 * KNUM];
    __shared__ __align__(16) __half out_s[KTOT];
    const int t  = threadIdx.x;
    const int o  = blockIdx.x;
    const int b0 = blockIdx.y * 16;

#pragma unroll
    for (int i = 0; i < 9; ++i) {
        int idx4 = i * 256 + t;
        int k = idx4 / 288;
        int r = idx4 - k * 288;
        float4 v = ((const float4*)kw)[((size_t)k * COUT + o) * 288 + r];
        __half2* d = (__half2*)(kw_s + k * KTOT + r * 4);
        d[0] = __floats2half2_rn(v.x, v.y);
        d[1] = __floats2half2_rn(v.z, v.w);
    }
    if (t < 128) sal[t] = g_alphas[b0 * KNUM + t];
    __syncthreads();

    for (int bb = 0; bb < 16; ++bb) {
#pragma unroll
        for (int i = 0; i < 3; ++i) {
            int jp = i * 256 + t;
            if (jp < 576) {
                float a0 = 0.f, a1 = 0.f;
#pragma unroll
                for (int k = 0; k < KNUM; ++k) {
                    float2 wv = __half22float2(*(const __half2*)(kw_s + k * KTOT + jp * 2));
                    float al = sal[bb * KNUM + k];
                    a0 += al * wv.x;
                    a1 += al * wv.y;
                }
                int j0 = jp * 2;
                int ci0 = j0 / 9, tap0 = j0 - ci0 * 9;
                int j1 = j0 + 1;
                int ci1 = j1 / 9, tap1 = j1 - ci1 * 9;
                out_s[(tap0 * 2 + (ci0 >> 6)) * 64 + (ci0 & 63)] = __float2half_rn(a0);
                out_s[(tap1 * 2 + (ci1 >> 6)) * 64 + (ci1 & 63)] = __float2half_rn(a1);
            }
        }
        __syncthreads();
        if (t < 144) {
            int seg = t >> 3, part = t & 7;
            *(uint4*)(g_aggw + (size_t)(b0 + bb) * (COUT * KTOT) + seg * 8192 + o * 64 + part * 8)
                = *(const uint4*)(out_s + seg * 64 + part * 8);
        }
        __syncthreads();
    }
}

// ================= kernel 3b: repack weights into mma-fragment layout ============
// out uint4 oidx = wn*512 + ks*128 + bt*32 + lane holds (b0e,b1e,b0o,b1o) for that
// (ks,bt,lane) of the chunk: n_e = wn*64+bt*16+(lane>>2), kb = ks*16+(lane&3)*2.
__global__ void __launch_bounds__(256) repack_kernel() {
    const int kc = blockIdx.x;       // 0..17
    const int b  = blockIdx.y;       // 0..31
    const __half* src = g_aggw + ((size_t)b * NCHUNK + kc) * 8192;
    uint4* dst = g_aggw2 + ((size_t)b * NCHUNK + kc) * 1024;
    const int t = threadIdx.x;
#pragma unroll
    for (int i = 0; i < 4; ++i) {
        int oidx = i * 256 + t;
        int lane = oidx & 31;
        int bt   = (oidx >> 5) & 3;
        int ks   = (oidx >> 7) & 3;
        int wn   = oidx >> 9;
        int ne   = wn * 64 + bt * 16 + (lane >> 2);
        int kb   = ks * 16 + (lane & 3) * 2;
        uint4 v;
        v.x = *(const uint32_t*)(src + ne * 64 + kb);
        v.y = *(const uint32_t*)(src + ne * 64 + kb + 8);
        v.z = *(const uint32_t*)(src + (ne + 8) * 64 + kb);
        v.w = *(const uint32_t*)(src + (ne + 8) * 64 + kb + 8);
        dst[oidx] = v;
    }
}

// ================= kernel 4: conv — resident-x, reg-B implicit GEMM ==============
__device__ __forceinline__ void ldsm_x4(uint32_t& r0, uint32_t& r1, uint32_t& r2, uint32_t& r3,
                                        uint32_t addr) {
    asm volatile("ldmatrix.sync.aligned.m8n8.x4.shared.b16 {%0,%1,%2,%3}, [%4];"
                 : "=r"(r0), "=r"(r1), "=r"(r2), "=r"(r3) : "r"(addr));
}
__device__ __forceinline__ void mma16816(float* c, uint32_t a0, uint32_t a1, uint32_t a2,
                                         uint32_t a3, uint32_t b0, uint32_t b1) {
    asm volatile(
        "mma.sync.aligned.m16n8k16.row.col.f32.f16.f16.f32 "
        "{%0,%1,%2,%3}, {%4,%5,%6,%7}, {%8,%9}, {%0,%1,%2,%3};"
        : "+f"(c[0]), "+f"(c[1]), "+f"(c[2]), "+f"(c[3])
        : "r"(a0), "r"(a1), "r"(a2), "r"(a3), "r"(b0), "r"(b1));
}
__device__ __forceinline__ void cp16(uint32_t dst, const void* src, uint32_t srcsz) {
    asm volatile("cp.async.cg.shared.global [%0], [%1], 16, %2;"
                 :: "r"(dst), "l"(src), "r"(srcsz) : "memory");
}

extern __shared__ char conv_dyn[];

// CTA = (tile of 128 positions = 2 image rows, sample b). 256 threads, 8 warps.
__global__ void __launch_bounds__(256, 2) conv_kernel(float* __restrict__ out) {
    __shared__ float bias_s[COUT];
    const int t    = threadIdx.x;
    const int wid  = t >> 5;
    const int lane = t & 31;
    const int tile = blockIdx.x;     // 0..31
    const int b    = blockIdx.y;     // 0..31

    if (t < COUT) bias_s[t] = g_aggb[b * COUT + t];

    const uint32_t dynbase = smem_u32(conv_dyn);
    const uint32_t xsb = dynbase;
    const uint32_t zsb = dynbase + ZOFF;

    const __half* xb = g_x16 + (size_t)b * HWTOT * CIN;
    const uint4*  wb2 = g_aggw2 + (size_t)b * NCHUNK * 1024;

    if (t < 16) *(uint4*)(conv_dyn + ZOFF + t * 16) = make_uint4(0u, 0u, 0u, 0u);

    // ---- x tile: 4 image rows (tile*2-1 .. tile*2+2), 16B-block XOR swizzle ----
#pragma unroll
    for (int i = 0; i < 16; ++i) {
        int idx = i * 256 + t;               // 4096 16B-blocks
        int smemrow = idx >> 4;              // 0..255
        int blk = idx & 15;
        int lrow = smemrow >> 6;
        int w    = smemrow & 63;
        int srcrow = tile * 2 - 1 + lrow;
        bool v = (unsigned)srcrow < 64u;
        uint32_t dst = xsb + smemrow * 256 + ((blk ^ (smemrow & 15)) << 4);
        const __half* src = v ? (xb + ((size_t)(srcrow * 64 + w) * CIN) + blk * 8) : xb;
        cp16(dst, src, v ? 16u : 0u);
    }
    asm volatile("cp.async.commit_group;" ::: "memory");

    // warp tiling: 4 (M) x 2 (N); warp tile = M32 x N64
    const int wm = wid >> 1;
    const int wn = wid & 1;
    const int m0 = wm * 32;

    float acc[2][8][4];
#pragma unroll
    for (int mt = 0; mt < 2; ++mt)
#pragma unroll
        for (int nt = 0; nt < 8; ++nt)
#pragma unroll
            for (int j = 0; j < 4; ++j) acc[mt][nt][j] = 0.f;

    int mrowhi[2], mpw[2];
#pragma unroll
    for (int mt = 0; mt < 2; ++mt) {
        int m = m0 + mt * 16 + (lane & 15);
        mrowhi[mt] = m >> 6;                 // 0..1
        mpw[mt]    = m & 63;
    }
    const int cq = lane >> 4;

    // B fragment pointer for this (wn, lane)
    const uint4* wlane = wb2 + wn * 512 + lane;

    // prefetch first B step (chunk 0, ks 0)
    uint4 bu[4];
#pragma unroll
    for (int bt = 0; bt < 4; ++bt) bu[bt] = wlane[bt * 32];

    asm volatile("cp.async.wait_group 0;" ::: "memory");
    __syncthreads();                         // x tile visible

#pragma unroll 1
    for (int kc = 0; kc < NCHUNK; ++kc) {
        const int tap   = kc >> 1;
        const int chalf = kc & 1;
        const int rtap  = (tap * 11) >> 5;
        const int stap  = tap - rtap * 3;

        uint32_t arow[2];
        int akey[2];
#pragma unroll
        for (int mt = 0; mt < 2; ++mt) {
            int lrow = mrowhi[mt] + rtap;     // 0..3
            int iw   = mpw[mt] + stap - 1;
            bool v = (unsigned)iw < 64u;
            int smemrow = lrow * 64 + iw;
            arow[mt] = v ? (xsb + smemrow * 256) : zsb;
            akey[mt] = v ? (smemrow & 15) : 0;
        }

#pragma unroll
        for (int ks = 0; ks < 4; ++ks) {
            // one-ahead prefetch of next (kc,ks) B fragments
            uint4 bn[4];
            int nstep = kc * 4 + ks + 1;
            if (nstep < NCHUNK * 4) {
                const uint4* ws = wlane + (size_t)(nstep >> 2) * 1024 + (nstep & 3) * 128;
#pragma unroll
                for (int bt = 0; bt < 4; ++bt) bn[bt] = ws[bt * 32];
            }

            const int blk = chalf * 8 + ks * 2 + cq;
            uint32_t A0[4], A1[4];
            ldsm_x4(A0[0], A0[1], A0[2], A0[3], arow[0] + ((blk ^ akey[0]) << 4));
            ldsm_x4(A1[0], A1[1], A1[2], A1[3], arow[1] + ((blk ^ akey[1]) << 4));
#pragma unroll
            for (int bt = 0; bt < 4; ++bt) {
                mma16816(acc[0][2 * bt],     A0[0], A0[1], A0[2], A0[3], bu[bt].x, bu[bt].y);
                mma16816(acc[0][2 * bt + 1], A0[0], A0[1], A0[2], A0[3], bu[bt].z, bu[bt].w);
                mma16816(acc[1][2 * bt],     A1[0], A1[1], A1[2], A1[3], bu[bt].x, bu[bt].y);
                mma16816(acc[1][2 * bt + 1], A1[0], A1[1], A1[2], A1[3], bu[bt].z, bu[bt].w);
            }
#pragma unroll
            for (int bt = 0; bt < 4; ++bt) bu[bt] = bn[bt];
        }
    }
    __syncthreads();                          // protect x region before F overwrite

    // ---- epilogue: F[o_local][p] transposed tile, stride 132 words ----
    float* F = (float*)conv_dyn;              // 64 x 132 floats = 33792 B
    float* outb = out + (size_t)b * COUT * HWTOT + tile * 128;
#pragma unroll
    for (int orr = 0; orr < 2; ++orr) {
        if (wn == orr) {
#pragma unroll
            for (int mt = 0; mt < 2; ++mt)
#pragma unroll
                for (int nt = 0; nt < 8; ++nt) {
                    int colb = nt * 8 + 2 * (lane & 3);
                    int row  = m0 + mt * 16 + (lane >> 2);
                    F[colb * 132 + row]           = acc[mt][nt][0];
                    F[(colb + 1) * 132 + row]     = acc[mt][nt][1];
                    F[colb * 132 + row + 8]       = acc[mt][nt][2];
                    F[(colb + 1) * 132 + row + 8] = acc[mt][nt][3];
                }
        }
        __syncthreads();
#pragma unroll
        for (int i = 0; i < 8; ++i) {
            int e = i * 256 + t;              // 2048 float4 units
            int ol = e >> 5;                  // 0..63
            int pp = (e & 31) * 4;
            float4 v = *(const float4*)&F[ol * 132 + pp];
            float bb = bias_s[orr * 64 + ol];
            v.x += bb; v.y += bb; v.z += bb; v.w += bb;
            *(float4*)(outb + (size_t)(orr * 64 + ol) * HWTOT + pp) = v;
        }
        __syncthreads();
    }
}

// ================= launch =================
extern "C" void kernel_launch(void* const* d_in, const int* in_sizes, int n_in,
                              void* d_out, int out_size) {
    (void)out_size;
    const float* x = nullptr; const float* prompt = nullptr;
    const float* w1 = nullptr; const float* b1 = nullptr;
    const float* w2 = nullptr; const float* b2 = nullptr;
    const float* kw = nullptr; const float* kb = nullptr;
    for (int i = 0; i < n_in; ++i) {
        const float* ptr = (const float*)d_in[i];
        switch (in_sizes[i]) {
            case 16777216: x = ptr; break;
            case 4096:     prompt = ptr; break;
            case 65536:    w1 = ptr; break;
            case 262144:   w2 = ptr; break;
            case 1179648:  kw = ptr; break;
            case 1024:     kb = ptr; break;
            case 512:      if (!b1) b1 = ptr; else b2 = ptr; break;
            default: break;
        }
    }
    float* out = (float*)d_out;

    static bool attr_set = false;
    if (!attr_set) {
        cudaFuncSetAttribute(conv_kernel, cudaFuncAttributeMaxDynamicSharedMemorySize, DYNSM);
        attr_set = true;
    }

    convert_kernel<<<dim3(HWTOT / 128, B_), 256>>>(x);
    mlp_kernel<<<B_, 512>>>(prompt, w1, b1, w2, b2, kb);
    aggw_kernel<<<dim3(COUT, 2), 256>>>(kw);
    repack_kernel<<<dim3(NCHUNK, B_), 256>>>();
    conv_kernel<<<dim3(32, B_), 256, DYNSM>>>(out);
}

// round 9
// speedup vs baseline: 1.1313x; 1.0387x over previous
#include <cuda_runtime.h>
#include <cuda_fp16.h>
#include <cstdint>

// ---------------- problem constants ----------------
#define B_    32
#define CIN   128
#define KNUM  8
#define COUT  128
#define HIDD  512
#define KTOT  1152          // CIN * 9
#define HWTOT 4096          // 64*64
#define NCHUNK 18           // 1152 / 64 (tap-major: 9 taps x 2 channel halves)
// conv smem: x tile only (4 image rows x 64 w x 256B) + 256B zero block
#define XSSZ  (4 * 64 * 256)          // 65536
#define ZOFF  XSSZ
#define DYNSM (XSSZ + 256)            // 65792 -> 2 CTAs/SM

// ---------------- scratch (device globals; no allocs) ----------------
__device__ __align__(16) float  g_pool_part[B_ * 32 * CIN];
__device__ __align__(16) float  g_alphas[B_ * KNUM];
__device__ __align__(16) float  g_aggb [B_ * COUT];
// fragment-permuted weights: [b][kc][wn(2)][ks(4)][bt(4)][lane(32)] x uint4
__device__ __align__(16) uint4  g_aggw2[(size_t)B_ * NCHUNK * 1024];
// x in NHWC fp16: [b][h][w][c]
__device__ __align__(16) __half g_x16  [(size_t)B_ * HWTOT * CIN];

__device__ __forceinline__ uint32_t smem_u32(const void* p) {
    return (uint32_t)__cvta_generic_to_shared(p);
}
__device__ __forceinline__ float warpsum(float v) {
#pragma unroll
    for (int o = 16; o; o >>= 1) v += __shfl_xor_sync(0xffffffffu, v, o);
    return v;
}

// ================= kernel 1: NCHW fp32 -> NHWC fp16 + pool partials ==============
__global__ void __launch_bounds__(256) convert_kernel(const float* __restrict__ x) {
    __shared__ char sm[128 * 256];
    const int t = threadIdx.x;
    const int tile = blockIdx.x;
    const int pos0 = tile * 128;
    const int b = blockIdx.y;
    const float* xb = x + ((size_t)b * CIN) * HWTOT;

#pragma unroll 4
    for (int i = 0; i < 64; ++i) {
        int e = i * 256 + t;
        int c = e >> 7;
        int p = e & 127;
        float v = xb[(size_t)c * HWTOT + pos0 + p];
        int boff = p * 256 + ((c * 2) ^ ((p & 31) << 2));
        *(__half*)(sm + boff) = __float2half_rn(v);
    }
    __syncthreads();
    if (t < 64) {
        float s0 = 0.f, s1 = 0.f;
#pragma unroll 8
        for (int p = 0; p < 128; ++p) {
            int boff = p * 256 + ((t * 4) ^ ((p & 31) << 2));
            __half2 h = *(const __half2*)(sm + boff);
            float2 f = __half22float2(h);
            s0 += f.x; s1 += f.y;
        }
        g_pool_part[(b * 32 + tile) * CIN + 2 * t]     = s0;
        g_pool_part[(b * 32 + tile) * CIN + 2 * t + 1] = s1;
    }
    __syncthreads();
    uint32_t* dstw = (uint32_t*)(g_x16 + ((size_t)b * HWTOT + pos0) * CIN);
#pragma unroll
    for (int i = 0; i < 32; ++i) {
        int e = i * 256 + t;
        int p = e >> 6;
        int wj = e & 63;
        uint32_t w = *(const uint32_t*)(sm + p * 256 + ((wj * 4) ^ ((p & 31) << 2)));
        dstw[p * 64 + wj] = w;
    }
}

// ================= kernel 2: MLP + scores + softmax + bias agg =================
__global__ void mlp_kernel(const float* __restrict__ prompt,
                           const float* __restrict__ w1, const float* __restrict__ b1,
                           const float* __restrict__ w2, const float* __restrict__ b2,
                           const float* __restrict__ kbias) {
    int b = blockIdx.x;
    int tid = threadIdx.x, wid = tid >> 5, lane = tid & 31;
    __shared__ float sp[CIN], sh[HIDD], ss[HIDD], ssc[KNUM], sal[KNUM];
    if (tid < CIN) {
        float s = 0.f;
#pragma unroll 8
        for (int tl = 0; tl < 32; ++tl) s += g_pool_part[(b * 32 + tl) * CIN + tid];
        sp[tid] = s * (1.f / (float)HWTOT);
    }
    __syncthreads();
    for (int j = wid; j < HIDD; j += 16) {
        float p = 0.f;
        for (int c = lane; c < CIN; c += 32) p += sp[c] * w1[j * CIN + c];
        p = warpsum(p);
        if (lane == 0) sh[j] = fmaxf(p + b1[j], 0.f);
    }
    __syncthreads();
    for (int j = wid; j < HIDD; j += 16) {
        float p = 0.f;
        for (int c = lane; c < HIDD; c += 32) p += sh[c] * w2[j * HIDD + c];
        p = warpsum(p);
        if (lane == 0) ss[j] = p + b2[j];
    }
    __syncthreads();
    if (wid < KNUM) {
        float p = 0.f;
        for (int j = lane; j < HIDD; j += 32) p += ss[j] * prompt[wid * HIDD + j];
        p = warpsum(p);
        if (lane == 0) ssc[wid] = p;
    }
    __syncthreads();
    if (tid == 0) {
        float mx = -1e30f;
#pragma unroll
        for (int k = 0; k < KNUM; k++) mx = fmaxf(mx, ssc[k]);
        float den = 0.f, e[KNUM];
#pragma unroll
        for (int k = 0; k < KNUM; k++) { e[k] = expf(ssc[k] - mx); den += e[k]; }
#pragma unroll
        for (int k = 0; k < KNUM; k++) sal[k] = e[k] / den;
    }
    __syncthreads();
    if (tid < KNUM) g_alphas[b * KNUM + tid] = sal[tid];
    if (tid < COUT) {
        float a = 0.f;
#pragma unroll
        for (int k = 0; k < KNUM; k++) a += sal[k] * kbias[k * COUT + tid];
        g_aggb[b * COUT + tid] = a;
    }
}

// ================= kernel 3: fused weight agg + fragment repack =================
// Block = (o-pair pi -> (o_lo, o_lo+8), 16-sample group). Stages kw rows for both
// o's, computes chunk-ordered agg weights, emits mma-fragment uint4s directly.
__global__ void __launch_bounds__(256) aggw_kernel(const float* __restrict__ kw) {
    __shared__ __align__(4) __half kw_s[2 * KNUM * KTOT];   // 36864 B
    __shared__ float sal[16 * KNUM];                         // 512 B
    __shared__ __align__(4) __half out_s[2 * KTOT];          // 4608 B
    const int t  = threadIdx.x;
    const int pi = blockIdx.x;                // 0..63
    const int b0 = blockIdx.y * 16;
    const int o_lo = ((pi >> 3) << 4) + (pi & 7);   // bit3 clear
    // fragment coords for this o-pair
    const int wn = o_lo >> 6;
    const int bt = (o_lo >> 4) & 3;
    const int r  = o_lo & 7;

    // stage kw[k][o][:] for o in {o_lo, o_lo+8}, float4-coalesced
    const float4* kw4 = (const float4*)kw;
#pragma unroll
    for (int i = 0; i < 18; ++i) {
        int s = i * 256 + t;                  // < 4608
        int oo = s / 2304;
        int rem = s - oo * 2304;
        int k = rem / 288;
        int rr = rem - k * 288;
        int o = o_lo + oo * 8;
        float4 v = kw4[((size_t)k * COUT + o) * 288 + rr];
        __half2* d = (__half2*)(kw_s + (oo * KNUM + k) * KTOT + rr * 4);
        d[0] = __floats2half2_rn(v.x, v.y);
        d[1] = __floats2half2_rn(v.z, v.w);
    }
    if (t < 128) sal[t] = g_alphas[b0 * KNUM + t];
    __syncthreads();

    for (int bb = 0; bb < 16; ++bb) {
        // compute 2 o x 1152 (as 576 half2 pairs each), chunk-ordered into out_s
#pragma unroll
        for (int i = 0; i < 5; ++i) {
            int jp = i * 256 + t;             // < 1152 total pairs
            if (jp < 1152) {
                int oo  = jp / 576;
                int jpp = jp - oo * 576;
                float a0 = 0.f, a1 = 0.f;
#pragma unroll
                for (int k = 0; k < KNUM; ++k) {
                    float2 wv = __half22float2(
                        *(const __half2*)(kw_s + (oo * KNUM + k) * KTOT + jpp * 2));
                    float al = sal[bb * KNUM + k];
                    a0 += al * wv.x;
                    a1 += al * wv.y;
                }
                int j0 = jpp * 2;
                int ci0 = j0 / 9, tap0 = j0 - ci0 * 9;
                int j1 = j0 + 1;
                int ci1 = j1 / 9, tap1 = j1 - ci1 * 9;
                out_s[oo * KTOT + (tap0 * 2 + (ci0 >> 6)) * 64 + (ci0 & 63)] = __float2half_rn(a0);
                out_s[oo * KTOT + (tap1 * 2 + (ci1 >> 6)) * 64 + (ci1 & 63)] = __float2half_rn(a1);
            }
        }
        __syncthreads();

        // emit fragments: 18 kc x 16 (ks,q) = 288 uint4
        uint4* dstb = g_aggw2 + ((size_t)(b0 + bb) * NCHUNK) * 1024;
#pragma unroll
        for (int i = 0; i < 2; ++i) {
            int idx = i * 256 + t;
            if (idx < 288) {
                int kc = idx >> 4;
                int f  = idx & 15;
                int ks = f >> 2;
                int q  = f & 3;
                int kb = ks * 16 + q * 2;
                const __half* lo = out_s + kc * 64;
                const __half* hi = out_s + KTOT + kc * 64;
                uint4 v;
                v.x = *(const uint32_t*)(lo + kb);
                v.y = *(const uint32_t*)(lo + kb + 8);
                v.z = *(const uint32_t*)(hi + kb);
                v.w = *(const uint32_t*)(hi + kb + 8);
                dstb[(size_t)kc * 1024 + wn * 512 + ks * 128 + bt * 32 + (r * 4 + q)] = v;
            }
        }
        __syncthreads();
    }
}

// ================= kernel 4: conv — resident-x, reg-B implicit GEMM ==============
__device__ __forceinline__ void ldsm_x4(uint32_t& r0, uint32_t& r1, uint32_t& r2, uint32_t& r3,
                                        uint32_t addr) {
    asm volatile("ldmatrix.sync.aligned.m8n8.x4.shared.b16 {%0,%1,%2,%3}, [%4];"
                 : "=r"(r0), "=r"(r1), "=r"(r2), "=r"(r3) : "r"(addr));
}
__device__ __forceinline__ void mma16816(float* c, uint32_t a0, uint32_t a1, uint32_t a2,
                                         uint32_t a3, uint32_t b0, uint32_t b1) {
    asm volatile(
        "mma.sync.aligned.m16n8k16.row.col.f32.f16.f16.f32 "
        "{%0,%1,%2,%3}, {%4,%5,%6,%7}, {%8,%9}, {%0,%1,%2,%3};"
        : "+f"(c[0]), "+f"(c[1]), "+f"(c[2]), "+f"(c[3])
        : "r"(a0), "r"(a1), "r"(a2), "r"(a3), "r"(b0), "r"(b1));
}
__device__ __forceinline__ void cp16(uint32_t dst, const void* src, uint32_t srcsz) {
    asm volatile("cp.async.cg.shared.global [%0], [%1], 16, %2;"
                 :: "r"(dst), "l"(src), "r"(srcsz) : "memory");
}

extern __shared__ char conv_dyn[];

__global__ void __launch_bounds__(256, 2) conv_kernel(float* __restrict__ out) {
    __shared__ float bias_s[COUT];
    const int t    = threadIdx.x;
    const int wid  = t >> 5;
    const int lane = t & 31;
    const int tile = blockIdx.x;     // 0..31
    const int b    = blockIdx.y;     // 0..31

    if (t < COUT) bias_s[t] = g_aggb[b * COUT + t];

    const uint32_t dynbase = smem_u32(conv_dyn);
    const uint32_t xsb = dynbase;
    const uint32_t zsb = dynbase + ZOFF;

    const __half* xb = g_x16 + (size_t)b * HWTOT * CIN;
    const uint4*  wb2 = g_aggw2 + (size_t)b * NCHUNK * 1024;

    if (t < 16) *(uint4*)(conv_dyn + ZOFF + t * 16) = make_uint4(0u, 0u, 0u, 0u);

#pragma unroll
    for (int i = 0; i < 16; ++i) {
        int idx = i * 256 + t;
        int smemrow = idx >> 4;
        int blk = idx & 15;
        int lrow = smemrow >> 6;
        int w    = smemrow & 63;
        int srcrow = tile * 2 - 1 + lrow;
        bool v = (unsigned)srcrow < 64u;
        uint32_t dst = xsb + smemrow * 256 + ((blk ^ (smemrow & 15)) << 4);
        const __half* src = v ? (xb + ((size_t)(srcrow * 64 + w) * CIN) + blk * 8) : xb;
        cp16(dst, src, v ? 16u : 0u);
    }
    asm volatile("cp.async.commit_group;" ::: "memory");

    const int wm = wid >> 1;
    const int wn = wid & 1;
    const int m0 = wm * 32;

    float acc[2][8][4];
#pragma unroll
    for (int mt = 0; mt < 2; ++mt)
#pragma unroll
        for (int nt = 0; nt < 8; ++nt)
#pragma unroll
            for (int j = 0; j < 4; ++j) acc[mt][nt][j] = 0.f;

    int mrowhi[2], mpw[2];
#pragma unroll
    for (int mt = 0; mt < 2; ++mt) {
        int m = m0 + mt * 16 + (lane & 15);
        mrowhi[mt] = m >> 6;
        mpw[mt]    = m & 63;
    }
    const int cq = lane >> 4;

    const uint4* wlane = wb2 + wn * 512 + lane;

    uint4 bu[4];
#pragma unroll
    for (int bt = 0; bt < 4; ++bt) bu[bt] = wlane[bt * 32];

    asm volatile("cp.async.wait_group 0;" ::: "memory");
    __syncthreads();

#pragma unroll 1
    for (int kc = 0; kc < NCHUNK; ++kc) {
        const int tap   = kc >> 1;
        const int chalf = kc & 1;
        const int rtap  = (tap * 11) >> 5;
        const int stap  = tap - rtap * 3;

        uint32_t arow[2];
        int akey[2];
#pragma unroll
        for (int mt = 0; mt < 2; ++mt) {
            int lrow = mrowhi[mt] + rtap;
            int iw   = mpw[mt] + stap - 1;
            bool v = (unsigned)iw < 64u;
            int smemrow = lrow * 64 + iw;
            arow[mt] = v ? (xsb + smemrow * 256) : zsb;
            akey[mt] = v ? (smemrow & 15) : 0;
        }

#pragma unroll
        for (int ks = 0; ks < 4; ++ks) {
            uint4 bn[4];
            int nstep = kc * 4 + ks + 1;
            if (nstep < NCHUNK * 4) {
                const uint4* ws = wlane + (size_t)(nstep >> 2) * 1024 + (nstep & 3) * 128;
#pragma unroll
                for (int bt = 0; bt < 4; ++bt) bn[bt] = ws[bt * 32];
            }

            const int blk = chalf * 8 + ks * 2 + cq;
            uint32_t A0[4], A1[4];
            ldsm_x4(A0[0], A0[1], A0[2], A0[3], arow[0] + ((blk ^ akey[0]) << 4));
            ldsm_x4(A1[0], A1[1], A1[2], A1[3], arow[1] + ((blk ^ akey[1]) << 4));
#pragma unroll
            for (int bt = 0; bt < 4; ++bt) {
                mma16816(acc[0][2 * bt],     A0[0], A0[1], A0[2], A0[3], bu[bt].x, bu[bt].y);
                mma16816(acc[0][2 * bt + 1], A0[0], A0[1], A0[2], A0[3], bu[bt].z, bu[bt].w);
                mma16816(acc[1][2 * bt],     A1[0], A1[1], A1[2], A1[3], bu[bt].x, bu[bt].y);
                mma16816(acc[1][2 * bt + 1], A1[0], A1[1], A1[2], A1[3], bu[bt].z, bu[bt].w);
            }
#pragma unroll
            for (int bt = 0; bt < 4; ++bt) bu[bt] = bn[bt];
        }
    }
    __syncthreads();

    float* F = (float*)conv_dyn;
    float* outb = out + (size_t)b * COUT * HWTOT + tile * 128;
#pragma unroll
    for (int orr = 0; orr < 2; ++orr) {
        if (wn == orr) {
#pragma unroll
            for (int mt = 0; mt < 2; ++mt)
#pragma unroll
                for (int nt = 0; nt < 8; ++nt) {
                    int colb = nt * 8 + 2 * (lane & 3);
                    int row  = m0 + mt * 16 + (lane >> 2);
                    F[colb * 132 + row]           = acc[mt][nt][0];
                    F[(colb + 1) * 132 + row]     = acc[mt][nt][1];
                    F[colb * 132 + row + 8]       = acc[mt][nt][2];
                    F[(colb + 1) * 132 + row + 8] = acc[mt][nt][3];
                }
        }
        __syncthreads();
#pragma unroll
        for (int i = 0; i < 8; ++i) {
            int e = i * 256 + t;
            int ol = e >> 5;
            int pp = (e & 31) * 4;
            float4 v = *(const float4*)&F[ol * 132 + pp];
            float bb = bias_s[orr * 64 + ol];
            v.x += bb; v.y += bb; v.z += bb; v.w += bb;
            *(float4*)(outb + (size_t)(orr * 64 + ol) * HWTOT + pp) = v;
        }
        __syncthreads();
    }
}

// ================= launch =================
extern "C" void kernel_launch(void* const* d_in, const int* in_sizes, int n_in,
                              void* d_out, int out_size) {
    (void)out_size;
    const float* x = nullptr; const float* prompt = nullptr;
    const float* w1 = nullptr; const float* b1 = nullptr;
    const float* w2 = nullptr; const float* b2 = nullptr;
    const float* kw = nullptr; const float* kb = nullptr;
    for (int i = 0; i < n_in; ++i) {
        const float* ptr = (const float*)d_in[i];
        switch (in_sizes[i]) {
            case 16777216: x = ptr; break;
            case 4096:     prompt = ptr; break;
            case 65536:    w1 = ptr; break;
            case 262144:   w2 = ptr; break;
            case 1179648:  kw = ptr; break;
            case 1024:     kb = ptr; break;
            case 512:      if (!b1) b1 = ptr; else b2 = ptr; break;
            default: break;
        }
    }
    float* out = (float*)d_out;

    static bool attr_set = false;
    if (!attr_set) {
        cudaFuncSetAttribute(conv_kernel, cudaFuncAttributeMaxDynamicSharedMemorySize, DYNSM);
        attr_set = true;
    }

    convert_kernel<<<dim3(HWTOT / 128, B_), 256>>>(x);
    mlp_kernel<<<B_, 512>>>(prompt, w1, b1, w2, b2, kb);
    aggw_kernel<<<dim3(64, 2), 256>>>(kw);
    conv_kernel<<<dim3(32, B_), 256, DYNSM>>>(out);
}

// round 10
// speedup vs baseline: 1.5500x; 1.3701x over previous
#include <cuda_runtime.h>
#include <cuda_fp16.h>
#include <cstdint>

// ---------------- problem constants ----------------
#define B_    32
#define CIN   128
#define KNUM  8
#define COUT  128
#define HIDD  512
#define KTOT  1152          // CIN * 9
#define HWTOT 4096          // 64*64
#define NCHUNK 18           // 1152 / 64 (tap-major: 9 taps x 2 channel halves)
// conv smem: x tile only (4 image rows x 64 w x 256B) + 256B zero block
#define XSSZ  (4 * 64 * 256)          // 65536
#define ZOFF  XSSZ
#define DYNSM (XSSZ + 256)            // 65792 -> 2 CTAs/SM

// ---------------- scratch (device globals; no allocs) ----------------
__device__ __align__(16) float  g_pool_part[B_ * 32 * CIN];
__device__ __align__(16) float  g_alphas[B_ * KNUM];
__device__ __align__(16) float  g_aggb [B_ * COUT];
// fragment-permuted weights: [b][kc][wn(2)][ks(4)][bt(4)][lane(32)] x uint4
__device__ __align__(16) uint4  g_aggw2[(size_t)B_ * NCHUNK * 1024];
// x in NHWC fp16: [b][h][w][c]
__device__ __align__(16) __half g_x16  [(size_t)B_ * HWTOT * CIN];

__device__ __forceinline__ uint32_t smem_u32(const void* p) {
    return (uint32_t)__cvta_generic_to_shared(p);
}
__device__ __forceinline__ float warpsum(float v) {
#pragma unroll
    for (int o = 16; o; o >>= 1) v += __shfl_xor_sync(0xffffffffu, v, o);
    return v;
}

// ================= kernel 1: NCHW fp32 -> NHWC fp16 + pool (vectorized) ==========
// Tile = 128 positions x 128 channels. Thread cell = (channel pair c2, pos quad p4):
// 2x LDG.128 -> 4x STS.32 (half2) into 16B-block XOR-swizzled smem; pooling via
// shfl-reduce + smem atomicAdd (fp32); write-out 2048x LDS.128 + contiguous STG.128.
__global__ void __launch_bounds__(256) convert_kernel(const float* __restrict__ x) {
    __shared__ __align__(16) char sm[128 * 256];
    __shared__ float pool[CIN];
    const int t    = threadIdx.x;
    const int lane = t & 31;
    const int w    = t >> 5;
    const int tile = blockIdx.x;
    const int pos0 = tile * 128;
    const int b    = blockIdx.y;
    const float* xb = x + ((size_t)b * CIN) * HWTOT;

    if (t < CIN) pool[t] = 0.f;
    __syncthreads();

    const int p4  = (w & 3) * 8 + (lane & 7);     // pos quad 0..31
    const int wrd = lane >> 3;                    // word-in-block 0..3 (== c2&3)
    const int fkey = p4 & 15;                     // swizzle key (== (p>>2)&15)

#pragma unroll
    for (int i = 0; i < 8; ++i) {
        const int blk = i * 2 + (w >> 2);         // 16B block 0..15 (== c2>>2)
        const int c2  = blk * 4 + wrd;            // channel pair 0..63
        const int c   = c2 * 2;
        const float4 f0 = *(const float4*)(xb + (size_t)c * HWTOT + pos0 + p4 * 4);
        const float4 f1 = *(const float4*)(xb + (size_t)(c + 1) * HWTOT + pos0 + p4 * 4);

        // pooling partials (fp32, pre-conversion), reduce over the 8-lane c2-group
        float s0 = (f0.x + f0.y) + (f0.z + f0.w);
        float s1 = (f1.x + f1.y) + (f1.z + f1.w);
#pragma unroll
        for (int o = 1; o < 8; o <<= 1) {
            s0 += __shfl_xor_sync(0xffffffffu, s0, o);
            s1 += __shfl_xor_sync(0xffffffffu, s1, o);
        }
        if ((lane & 7) == 0) {
            atomicAdd(&pool[c], s0);
            atomicAdd(&pool[c + 1], s1);
        }

        // stores: half2 per position, conflict-free
        const int bbase = ((blk ^ fkey) << 4) + wrd * 4;
        *(__half2*)(sm + (p4 * 4 + 0) * 256 + bbase) = __floats2half2_rn(f0.x, f1.x);
        *(__half2*)(sm + (p4 * 4 + 1) * 256 + bbase) = __floats2half2_rn(f0.y, f1.y);
        *(__half2*)(sm + (p4 * 4 + 2) * 256 + bbase) = __floats2half2_rn(f0.z, f1.z);
        *(__half2*)(sm + (p4 * 4 + 3) * 256 + bbase) = __floats2half2_rn(f0.w, f1.w);
    }
    __syncthreads();

    // write-out: NHWC, fully coalesced
    uint4* dst = (uint4*)(g_x16 + ((size_t)b * HWTOT + pos0) * CIN);
#pragma unroll
    for (int i = 0; i < 8; ++i) {
        int e  = i * 256 + t;                     // 2048 uint4
        int p  = e >> 4;
        int cq = e & 15;
        uint4 v = *(const uint4*)(sm + p * 256 + ((cq ^ ((p >> 2) & 15)) << 4));
        dst[p * 16 + cq] = v;
    }
    if (t < CIN) g_pool_part[(b * 32 + tile) * CIN + t] = pool[t];
}

// ================= kernel 2: MLP + scores + softmax + bias agg (1024 thr) =========
__global__ void __launch_bounds__(1024) mlp_kernel(
        const float* __restrict__ prompt,
        const float* __restrict__ w1, const float* __restrict__ b1,
        const float* __restrict__ w2, const float* __restrict__ b2,
        const float* __restrict__ kbias) {
    int b = blockIdx.x;
    int tid = threadIdx.x, wid = tid >> 5, lane = tid & 31;
    __shared__ __align__(16) float sp[CIN];
    __shared__ __align__(16) float sh[HIDD];
    __shared__ __align__(16) float ss[HIDD];
    __shared__ float ssc[KNUM], sal[KNUM];
    if (tid < CIN) {
        float s = 0.f;
#pragma unroll 8
        for (int tl = 0; tl < 32; ++tl) s += g_pool_part[(b * 32 + tl) * CIN + tid];
        sp[tid] = s * (1.f / (float)HWTOT);
    }
    __syncthreads();
    // h = relu(pooled @ w1^T + b1): one float4 per lane
    for (int j = wid; j < HIDD; j += 32) {
        float4 wv = ((const float4*)w1)[j * 32 + lane];
        float4 pv = *(const float4*)&sp[lane * 4];
        float p = wv.x * pv.x + wv.y * pv.y + wv.z * pv.z + wv.w * pv.w;
        p = warpsum(p);
        if (lane == 0) sh[j] = fmaxf(p + b1[j], 0.f);
    }
    __syncthreads();
    // s = h @ w2^T + b2: 4 float4 per lane
    for (int j = wid; j < HIDD; j += 32) {
        float p = 0.f;
#pragma unroll
        for (int q = 0; q < 4; ++q) {
            float4 wv = ((const float4*)w2)[j * 128 + q * 32 + lane];
            float4 hv = *(const float4*)&sh[(q * 32 + lane) * 4];
            p += wv.x * hv.x + wv.y * hv.y + wv.z * hv.z + wv.w * hv.w;
        }
        p = warpsum(p);
        if (lane == 0) ss[j] = p + b2[j];
    }
    __syncthreads();
    if (wid < KNUM) {
        float p = 0.f;
#pragma unroll
        for (int q = 0; q < 4; ++q) {
            float4 pv = ((const float4*)prompt)[wid * 128 + q * 32 + lane];
            float4 sv = *(const float4*)&ss[(q * 32 + lane) * 4];
            p += pv.x * sv.x + pv.y * sv.y + pv.z * sv.z + pv.w * sv.w;
        }
        p = warpsum(p);
        if (lane == 0) ssc[wid] = p;
    }
    __syncthreads();
    if (tid == 0) {
        float mx = -1e30f;
#pragma unroll
        for (int k = 0; k < KNUM; k++) mx = fmaxf(mx, ssc[k]);
        float den = 0.f, e[KNUM];
#pragma unroll
        for (int k = 0; k < KNUM; k++) { e[k] = expf(ssc[k] - mx); den += e[k]; }
#pragma unroll
        for (int k = 0; k < KNUM; k++) sal[k] = e[k] / den;
    }
    __syncthreads();
    if (tid < KNUM) g_alphas[b * KNUM + tid] = sal[tid];
    if (tid < COUT) {
        float a = 0.f;
#pragma unroll
        for (int k = 0; k < KNUM; k++) a += sal[k] * kbias[k * COUT + tid];
        g_aggb[b * COUT + tid] = a;
    }
}

// ================= kernel 3: fused weight agg + fragment repack (unchanged) ======
__global__ void __launch_bounds__(256) aggw_kernel(const float* __restrict__ kw) {
    __shared__ __align__(4) __half kw_s[2 * KNUM * KTOT];
    __shared__ float sal[16 * KNUM];
    __shared__ __align__(4) __half out_s[2 * KTOT];
    const int t  = threadIdx.x;
    const int pi = blockIdx.x;
    const int b0 = blockIdx.y * 16;
    const int o_lo = ((pi >> 3) << 4) + (pi & 7);
    const int wn = o_lo >> 6;
    const int bt = (o_lo >> 4) & 3;
    const int r  = o_lo & 7;

    const float4* kw4 = (const float4*)kw;
#pragma unroll
    for (int i = 0; i < 18; ++i) {
        int s = i * 256 + t;
        int oo = s / 2304;
        int rem = s - oo * 2304;
        int k = rem / 288;
        int rr = rem - k * 288;
        int o = o_lo + oo * 8;
        float4 v = kw4[((size_t)k * COUT + o) * 288 + rr];
        __half2* d = (__half2*)(kw_s + (oo * KNUM + k) * KTOT + rr * 4);
        d[0] = __floats2half2_rn(v.x, v.y);
        d[1] = __floats2half2_rn(v.z, v.w);
    }
    if (t < 128) sal[t] = g_alphas[b0 * KNUM + t];
    __syncthreads();

    for (int bb = 0; bb < 16; ++bb) {
#pragma unroll
        for (int i = 0; i < 5; ++i) {
            int jp = i * 256 + t;
            if (jp < 1152) {
                int oo  = jp / 576;
                int jpp = jp - oo * 576;
                float a0 = 0.f, a1 = 0.f;
#pragma unroll
                for (int k = 0; k < KNUM; ++k) {
                    float2 wv = __half22float2(
                        *(const __half2*)(kw_s + (oo * KNUM + k) * KTOT + jpp * 2));
                    float al = sal[bb * KNUM + k];
                    a0 += al * wv.x;
                    a1 += al * wv.y;
                }
                int j0 = jpp * 2;
                int ci0 = j0 / 9, tap0 = j0 - ci0 * 9;
                int j1 = j0 + 1;
                int ci1 = j1 / 9, tap1 = j1 - ci1 * 9;
                out_s[oo * KTOT + (tap0 * 2 + (ci0 >> 6)) * 64 + (ci0 & 63)] = __float2half_rn(a0);
                out_s[oo * KTOT + (tap1 * 2 + (ci1 >> 6)) * 64 + (ci1 & 63)] = __float2half_rn(a1);
            }
        }
        __syncthreads();

        uint4* dstb = g_aggw2 + ((size_t)(b0 + bb) * NCHUNK) * 1024;
#pragma unroll
        for (int i = 0; i < 2; ++i) {
            int idx = i * 256 + t;
            if (idx < 288) {
                int kc = idx >> 4;
                int f  = idx & 15;
                int ks = f >> 2;
                int q  = f & 3;
                int kb = ks * 16 + q * 2;
                const __half* lo = out_s + kc * 64;
                const __half* hi = out_s + KTOT + kc * 64;
                uint4 v;
                v.x = *(const uint32_t*)(lo + kb);
                v.y = *(const uint32_t*)(lo + kb + 8);
                v.z = *(const uint32_t*)(hi + kb);
                v.w = *(const uint32_t*)(hi + kb + 8);
                dstb[(size_t)kc * 1024 + wn * 512 + ks * 128 + bt * 32 + (r * 4 + q)] = v;
            }
        }
        __syncthreads();
    }
}

// ================= kernel 4: conv — resident-x, reg-B implicit GEMM (unchanged) ===
__device__ __forceinline__ void ldsm_x4(uint32_t& r0, uint32_t& r1, uint32_t& r2, uint32_t& r3,
                                        uint32_t addr) {
    asm volatile("ldmatrix.sync.aligned.m8n8.x4.shared.b16 {%0,%1,%2,%3}, [%4];"
                 : "=r"(r0), "=r"(r1), "=r"(r2), "=r"(r3) : "r"(addr));
}
__device__ __forceinline__ void mma16816(float* c, uint32_t a0, uint32_t a1, uint32_t a2,
                                         uint32_t a3, uint32_t b0, uint32_t b1) {
    asm volatile(
        "mma.sync.aligned.m16n8k16.row.col.f32.f16.f16.f32 "
        "{%0,%1,%2,%3}, {%4,%5,%6,%7}, {%8,%9}, {%0,%1,%2,%3};"
        : "+f"(c[0]), "+f"(c[1]), "+f"(c[2]), "+f"(c[3])
        : "r"(a0), "r"(a1), "r"(a2), "r"(a3), "r"(b0), "r"(b1));
}
__device__ __forceinline__ void cp16(uint32_t dst, const void* src, uint32_t srcsz) {
    asm volatile("cp.async.cg.shared.global [%0], [%1], 16, %2;"
                 :: "r"(dst), "l"(src), "r"(srcsz) : "memory");
}

extern __shared__ char conv_dyn[];

__global__ void __launch_bounds__(256, 2) conv_kernel(float* __restrict__ out) {
    __shared__ float bias_s[COUT];
    const int t    = threadIdx.x;
    const int wid  = t >> 5;
    const int lane = t & 31;
    const int tile = blockIdx.x;
    const int b    = blockIdx.y;

    if (t < COUT) bias_s[t] = g_aggb[b * COUT + t];

    const uint32_t dynbase = smem_u32(conv_dyn);
    const uint32_t xsb = dynbase;
    const uint32_t zsb = dynbase + ZOFF;

    const __half* xb = g_x16 + (size_t)b * HWTOT * CIN;
    const uint4*  wb2 = g_aggw2 + (size_t)b * NCHUNK * 1024;

    if (t < 16) *(uint4*)(conv_dyn + ZOFF + t * 16) = make_uint4(0u, 0u, 0u, 0u);

#pragma unroll
    for (int i = 0; i < 16; ++i) {
        int idx = i * 256 + t;
        int smemrow = idx >> 4;
        int blk = idx & 15;
        int lrow = smemrow >> 6;
        int w    = smemrow & 63;
        int srcrow = tile * 2 - 1 + lrow;
        bool v = (unsigned)srcrow < 64u;
        uint32_t dst = xsb + smemrow * 256 + ((blk ^ (smemrow & 15)) << 4);
        const __half* src = v ? (xb + ((size_t)(srcrow * 64 + w) * CIN) + blk * 8) : xb;
        cp16(dst, src, v ? 16u : 0u);
    }
    asm volatile("cp.async.commit_group;" ::: "memory");

    const int wm = wid >> 1;
    const int wn = wid & 1;
    const int m0 = wm * 32;

    float acc[2][8][4];
#pragma unroll
    for (int mt = 0; mt < 2; ++mt)
#pragma unroll
        for (int nt = 0; nt < 8; ++nt)
#pragma unroll
            for (int j = 0; j < 4; ++j) acc[mt][nt][j] = 0.f;

    int mrowhi[2], mpw[2];
#pragma unroll
    for (int mt = 0; mt < 2; ++mt) {
        int m = m0 + mt * 16 + (lane & 15);
        mrowhi[mt] = m >> 6;
        mpw[mt]    = m & 63;
    }
    const int cq = lane >> 4;

    const uint4* wlane = wb2 + wn * 512 + lane;

    uint4 bu[4];
#pragma unroll
    for (int bt = 0; bt < 4; ++bt) bu[bt] = wlane[bt * 32];

    asm volatile("cp.async.wait_group 0;" ::: "memory");
    __syncthreads();

#pragma unroll 1
    for (int kc = 0; kc < NCHUNK; ++kc) {
        const int tap   = kc >> 1;
        const int chalf = kc & 1;
        const int rtap  = (tap * 11) >> 5;
        const int stap  = tap - rtap * 3;

        uint32_t arow[2];
        int akey[2];
#pragma unroll
        for (int mt = 0; mt < 2; ++mt) {
            int lrow = mrowhi[mt] + rtap;
            int iw   = mpw[mt] + stap - 1;
            bool v = (unsigned)iw < 64u;
            int smemrow = lrow * 64 + iw;
            arow[mt] = v ? (xsb + smemrow * 256) : zsb;
            akey[mt] = v ? (smemrow & 15) : 0;
        }

#pragma unroll
        for (int ks = 0; ks < 4; ++ks) {
            uint4 bn[4];
            int nstep = kc * 4 + ks + 1;
            if (nstep < NCHUNK * 4) {
                const uint4* ws = wlane + (size_t)(nstep >> 2) * 1024 + (nstep & 3) * 128;
#pragma unroll
                for (int bt = 0; bt < 4; ++bt) bn[bt] = ws[bt * 32];
            }

            const int blk = chalf * 8 + ks * 2 + cq;
            uint32_t A0[4], A1[4];
            ldsm_x4(A0[0], A0[1], A0[2], A0[3], arow[0] + ((blk ^ akey[0]) << 4));
            ldsm_x4(A1[0], A1[1], A1[2], A1[3], arow[1] + ((blk ^ akey[1]) << 4));
#pragma unroll
            for (int bt = 0; bt < 4; ++bt) {
                mma16816(acc[0][2 * bt],     A0[0], A0[1], A0[2], A0[3], bu[bt].x, bu[bt].y);
                mma16816(acc[0][2 * bt + 1], A0[0], A0[1], A0[2], A0[3], bu[bt].z, bu[bt].w);
                mma16816(acc[1][2 * bt],     A1[0], A1[1], A1[2], A1[3], bu[bt].x, bu[bt].y);
                mma16816(acc[1][2 * bt + 1], A1[0], A1[1], A1[2], A1[3], bu[bt].z, bu[bt].w);
            }
#pragma unroll
            for (int bt = 0; bt < 4; ++bt) bu[bt] = bn[bt];
        }
    }
    __syncthreads();

    float* F = (float*)conv_dyn;
    float* outb = out + (size_t)b * COUT * HWTOT + tile * 128;
#pragma unroll
    for (int orr = 0; orr < 2; ++orr) {
        if (wn == orr) {
#pragma unroll
            for (int mt = 0; mt < 2; ++mt)
#pragma unroll
                for (int nt = 0; nt < 8; ++nt) {
                    int colb = nt * 8 + 2 * (lane & 3);
                    int row  = m0 + mt * 16 + (lane >> 2);
                    F[colb * 132 + row]           = acc[mt][nt][0];
                    F[(colb + 1) * 132 + row]     = acc[mt][nt][1];
                    F[colb * 132 + row + 8]       = acc[mt][nt][2];
                    F[(colb + 1) * 132 + row + 8] = acc[mt][nt][3];
                }
        }
        __syncthreads();
#pragma unroll
        for (int i = 0; i < 8; ++i) {
            int e = i * 256 + t;
            int ol = e >> 5;
            int pp = (e & 31) * 4;
            float4 v = *(const float4*)&F[ol * 132 + pp];
            float bb = bias_s[orr * 64 + ol];
            v.x += bb; v.y += bb; v.z += bb; v.w += bb;
            *(float4*)(outb + (size_t)(orr * 64 + ol) * HWTOT + pp) = v;
        }
        __syncthreads();
    }
}

// ================= launch =================
extern "C" void kernel_launch(void* const* d_in, const int* in_sizes, int n_in,
                              void* d_out, int out_size) {
    (void)out_size;
    const float* x = nullptr; const float* prompt = nullptr;
    const float* w1 = nullptr; const float* b1 = nullptr;
    const float* w2 = nullptr; const float* b2 = nullptr;
    const float* kw = nullptr; const float* kb = nullptr;
    for (int i = 0; i < n_in; ++i) {
        const float* ptr = (const float*)d_in[i];
        switch (in_sizes[i]) {
            case 16777216: x = ptr; break;
            case 4096:     prompt = ptr; break;
            case 65536:    w1 = ptr; break;
            case 262144:   w2 = ptr; break;
            case 1179648:  kw = ptr; break;
            case 1024:     kb = ptr; break;
            case 512:      if (!b1) b1 = ptr; else b2 = ptr; break;
            default: break;
        }
    }
    float* out = (float*)d_out;

    static bool attr_set = false;
    if (!attr_set) {
        cudaFuncSetAttribute(conv_kernel, cudaFuncAttributeMaxDynamicSharedMemorySize, DYNSM);
        attr_set = true;
    }

    convert_kernel<<<dim3(HWTOT / 128, B_), 256>>>(x);
    mlp_kernel<<<B_, 1024>>>(prompt, w1, b1, w2, b2, kb);
    aggw_kernel<<<dim3(64, 2), 256>>>(kw);
    conv_kernel<<<dim3(32, B_), 256, DYNSM>>>(out);
}